// round 1
// baseline (speedup 1.0000x reference)
#include <cuda_runtime.h>

#define BB 32
#define NN 4096
#define DD 256
#define HH 8
#define TT 28
#define ROWS (BB * NN)
#define BLK 128

// ---------- packed f32x2 FMA (sm_100+): 2 fp32 MACs per instruction ----------
__device__ __forceinline__ float2 ffma2(float2 a, float2 b, float2 c) {
    float2 d;
    asm("{\n\t"
        ".reg .b64 ra, rb, rc, rd;\n\t"
        "mov.b64 ra, {%2, %3};\n\t"
        "mov.b64 rb, {%4, %5};\n\t"
        "mov.b64 rc, {%6, %7};\n\t"
        "fma.rn.f32x2 rd, ra, rb, rc;\n\t"
        "mov.b64 {%0, %1}, rd;\n\t"
        "}"
        : "=f"(d.x), "=f"(d.y)
        : "f"(a.x), "f"(a.y), "f"(b.x), "f"(b.y), "f"(c.x), "f"(c.y));
    return d;
}

__device__ __forceinline__ float fex2(float x) {
    float y; asm("ex2.approx.f32 %0, %1;" : "=f"(y) : "f"(x)); return y;
}
__device__ __forceinline__ float frcp(float x) {
    float y; asm("rcp.approx.f32 %0, %1;" : "=f"(y) : "f"(x)); return y;
}

#define L2E 1.4426950408889634f

// sigmoid of both lanes, sharing one reciprocal: 2 EX2 + 1 RCP
__device__ __forceinline__ float2 sigmoid2(float2 v) {
    float ea = fex2(-L2E * v.x);
    float eb = fex2(-L2E * v.y);
    float sa = 1.0f + ea, sb = 1.0f + eb;
    float ip = frcp(sa * sb);
    return make_float2(sb * ip, sa * ip);
}

// tanh of both lanes via exp(2x), sharing one reciprocal
__device__ __forceinline__ float2 tanh2(float2 v) {
    float ta = fex2(2.0f * L2E * v.x);
    float tb = fex2(2.0f * L2E * v.y);
    float pa = ta + 1.0f, pb = tb + 1.0f;
    float ip = frcp(pa * pb);
    return make_float2((ta - 1.0f) * pb * ip, (tb - 1.0f) * pa * ip);
}

struct Smem {
    float4 xs[BLK][8];      // staged x chunk (128 rows x 32 cols), XOR-swizzled
    float4 wproj[DD][4];    // packed: [d][q] = rows 4q..4q+3 of [Wp;Wg1] at col d
    float4 whh[HH][6];      // [j][q] = W_hh rows 4q..4q+3, col j
    float4 wih[6];          // w_ih[24]
    float4 bih[6];
    float4 bhh[6];
    float4 wg2[TT][2];      // Wg2 row t (8 floats)
    float  bg2[TT];
    float2 wo2[4];          // Wo pairs
    float2 bp2[4];          // bp pairs
    float2 bg12[4];         // bg1 pairs
    float  dc[TT];          // decay curve
    float  bo;
};

__global__ void __launch_bounds__(BLK)
horizon_kernel(const float* __restrict__ x, const float* __restrict__ last_step,
               const float* __restrict__ W_ih, const float* __restrict__ W_hh,
               const float* __restrict__ b_ih, const float* __restrict__ b_hh,
               const float* __restrict__ Wp, const float* __restrict__ bp,
               const float* __restrict__ Wo, const float* __restrict__ bo,
               const float* __restrict__ Wg1, const float* __restrict__ bg1,
               const float* __restrict__ Wg2, const float* __restrict__ bg2,
               const float* __restrict__ log_decay, float* __restrict__ out) {
    __shared__ Smem s;
    const int tid = threadIdx.x;
    const int rb = blockIdx.x * BLK;

    // ---------------- weight prep (packed pair layouts) ----------------
    for (int i = tid; i < DD * 4; i += BLK) {
        int d = i >> 2, q = i & 3;
        const float* Wsrc = (q < 2) ? (Wp + (4 * q) * DD) : (Wg1 + (4 * q - 8) * DD);
        float4 w;
        w.x = Wsrc[d];
        w.y = Wsrc[DD + d];
        w.z = Wsrc[2 * DD + d];
        w.w = Wsrc[3 * DD + d];
        s.wproj[d][q] = w;
    }
    if (tid < 48) {
        int j = tid / 6, q = tid % 6;
        s.whh[j][q] = make_float4(W_hh[(4 * q + 0) * HH + j], W_hh[(4 * q + 1) * HH + j],
                                  W_hh[(4 * q + 2) * HH + j], W_hh[(4 * q + 3) * HH + j]);
    }
    if (tid < 6) {
        s.wih[tid] = ((const float4*)W_ih)[tid];
        s.bih[tid] = ((const float4*)b_ih)[tid];
        s.bhh[tid] = ((const float4*)b_hh)[tid];
    }
    if (tid < 56) s.wg2[tid >> 1][tid & 1] = ((const float4*)Wg2)[tid];
    if (tid < TT) {
        s.bg2[tid] = bg2[tid];
        float edc = __expf(log_decay[0]);
        s.dc[tid] = __expf(-edc * (float)(tid + 1));
    }
    if (tid < 4) {
        s.wo2[tid]  = ((const float2*)Wo)[tid];
        s.bp2[tid]  = ((const float2*)bp)[tid];
        s.bg12[tid] = ((const float2*)bg1)[tid];
    }
    if (tid == 0) s.bo = bo[0];
    __syncthreads();

    // ---------------- projections: h0 (Wp) and g1pre (Wg1) ----------------
    float2 acc[8];
#pragma unroll
    for (int p = 0; p < 4; p++) acc[p] = s.bp2[p];
#pragma unroll
    for (int p = 0; p < 4; p++) acc[4 + p] = s.bg12[p];

#pragma unroll 1
    for (int c = 0; c < 8; c++) {
        __syncthreads();
        // cooperative coalesced load of 128 rows x 32 cols
#pragma unroll
        for (int k = 0; k < 8; k++) {
            int idx = k * BLK + tid;          // 0..1023 float4s
            int r = idx >> 3, q = idx & 7;
            float4 v = ((const float4*)(x + (size_t)(rb + r) * DD + c * 32))[q];
            s.xs[r][q ^ (r & 7)] = v;
        }
        __syncthreads();
#pragma unroll
        for (int q = 0; q < 8; q++) {
            float4 xv = s.xs[tid][q ^ (tid & 7)];
            float xe0 = xv.x, xe1 = xv.y, xe2 = xv.z, xe3 = xv.w;
            const float4* wd = s.wproj[(c << 5) + (q << 2)];
#pragma unroll
            for (int e = 0; e < 4; e++) {
                float xs_e = (e == 0) ? xe0 : (e == 1) ? xe1 : (e == 2) ? xe2 : xe3;
                float2 xd = make_float2(xs_e, xs_e);
                float4 w0 = wd[e * 4 + 0], w1 = wd[e * 4 + 1];
                float4 w2 = wd[e * 4 + 2], w3 = wd[e * 4 + 3];
                acc[0] = ffma2(make_float2(w0.x, w0.y), xd, acc[0]);
                acc[1] = ffma2(make_float2(w0.z, w0.w), xd, acc[1]);
                acc[2] = ffma2(make_float2(w1.x, w1.y), xd, acc[2]);
                acc[3] = ffma2(make_float2(w1.z, w1.w), xd, acc[3]);
                acc[4] = ffma2(make_float2(w2.x, w2.y), xd, acc[4]);
                acc[5] = ffma2(make_float2(w2.z, w2.w), xd, acc[5]);
                acc[6] = ffma2(make_float2(w3.x, w3.y), xd, acc[6]);
                acc[7] = ffma2(make_float2(w3.z, w3.w), xd, acc[7]);
            }
        }
    }

    float2 h2[4];
#pragma unroll
    for (int p = 0; p < 4; p++) h2[p] = acc[p];
    float2 g1p[4];
#pragma unroll
    for (int p = 0; p < 4; p++)
        g1p[p] = make_float2(fmaxf(acc[4 + p].x, 0.0f), fmaxf(acc[4 + p].y, 0.0f));

    // ---------------- GRU rollout fused with gate + decay + output ----------------
    float last = last_step[rb + tid];
    float cur = last;
    float* outrow = out + (size_t)(rb + tid) * TT;
    float4 obuf = make_float4(0.f, 0.f, 0.f, 0.f);

#pragma unroll 4
    for (int t = 0; t < TT; t++) {
        // gh = h @ W_hh^T + b_hh  (12 packed pairs over k = 0..23)
        float2 g[12];
#pragma unroll
        for (int q = 0; q < 6; q++) {
            float4 b4 = s.bhh[q];
            g[2 * q]     = make_float2(b4.x, b4.y);
            g[2 * q + 1] = make_float2(b4.z, b4.w);
        }
#pragma unroll
        for (int j = 0; j < 8; j++) {
            float hj = (j & 1) ? h2[j >> 1].y : h2[j >> 1].x;
            float2 hd = make_float2(hj, hj);
#pragma unroll
            for (int q = 0; q < 6; q++) {
                float4 w4 = s.whh[j][q];
                g[2 * q]     = ffma2(make_float2(w4.x, w4.y), hd, g[2 * q]);
                g[2 * q + 1] = ffma2(make_float2(w4.z, w4.w), hd, g[2 * q + 1]);
            }
        }
        // gi = cur * w_ih + b_ih
        float2 curd = make_float2(cur, cur);
        float2 gi[12];
#pragma unroll
        for (int q = 0; q < 6; q++) {
            float4 wa = s.wih[q];
            float4 ba = s.bih[q];
            gi[2 * q]     = ffma2(make_float2(wa.x, wa.y), curd, make_float2(ba.x, ba.y));
            gi[2 * q + 1] = ffma2(make_float2(wa.z, wa.w), curd, make_float2(ba.z, ba.w));
        }
        // gates
        float2 r2[4], z2[4], n2[4];
#pragma unroll
        for (int p = 0; p < 4; p++)
            r2[p] = sigmoid2(make_float2(gi[p].x + g[p].x, gi[p].y + g[p].y));
#pragma unroll
        for (int p = 0; p < 4; p++)
            z2[p] = sigmoid2(make_float2(gi[4 + p].x + g[4 + p].x, gi[4 + p].y + g[4 + p].y));
#pragma unroll
        for (int p = 0; p < 4; p++)
            n2[p] = tanh2(ffma2(r2[p], g[8 + p], gi[8 + p]));
        // h_new = n + z*(h - n);  pred = h_new . Wo + bo
        float2 pacc = make_float2(0.0f, 0.0f);
#pragma unroll
        for (int p = 0; p < 4; p++) {
            float2 dmn = make_float2(h2[p].x - n2[p].x, h2[p].y - n2[p].y);
            float2 hn = ffma2(z2[p], dmn, n2[p]);
            h2[p] = hn;
            pacc = ffma2(hn, s.wo2[p], pacc);
        }
        float pred = pacc.x + pacc.y + s.bo;
        cur = pred;

        // gate_t = sigmoid(g1 . Wg2[t] + bg2[t])
        float4 wg0 = s.wg2[t][0], wg1v = s.wg2[t][1];
        float2 lacc = ffma2(g1p[0], make_float2(wg0.x, wg0.y), make_float2(s.bg2[t], 0.0f));
        lacc = ffma2(g1p[1], make_float2(wg0.z, wg0.w), lacc);
        lacc = ffma2(g1p[2], make_float2(wg1v.x, wg1v.y), lacc);
        lacc = ffma2(g1p[3], make_float2(wg1v.z, wg1v.w), lacc);
        float lg = lacc.x + lacc.y;
        float gate = frcp(1.0f + fex2(-L2E * lg));

        float gd = last * s.dc[t];
        float f = fmaf(gate, pred - gd, gd);  // gate*pred + (1-gate)*gd

        if ((t & 3) == 0) obuf.x = f;
        else if ((t & 3) == 1) obuf.y = f;
        else if ((t & 3) == 2) obuf.z = f;
        else {
            obuf.w = f;
            ((float4*)outrow)[t >> 2] = obuf;
        }
    }
}

extern "C" void kernel_launch(void* const* d_in, const int* in_sizes, int n_in,
                              void* d_out, int out_size) {
    const float* x         = (const float*)d_in[0];
    const float* last_step = (const float*)d_in[1];
    const float* W_ih      = (const float*)d_in[2];
    const float* W_hh      = (const float*)d_in[3];
    const float* b_ih      = (const float*)d_in[4];
    const float* b_hh      = (const float*)d_in[5];
    const float* Wp        = (const float*)d_in[6];
    const float* bp        = (const float*)d_in[7];
    const float* Wo        = (const float*)d_in[8];
    const float* bo        = (const float*)d_in[9];
    const float* Wg1       = (const float*)d_in[10];
    const float* bg1       = (const float*)d_in[11];
    const float* Wg2       = (const float*)d_in[12];
    const float* bg2       = (const float*)d_in[13];
    const float* log_decay = (const float*)d_in[14];
    float* out = (float*)d_out;

    horizon_kernel<<<ROWS / BLK, BLK>>>(x, last_step, W_ih, W_hh, b_ih, b_hh,
                                        Wp, bp, Wo, bo, Wg1, bg1, Wg2, bg2,
                                        log_decay, out);
}

// round 2
// speedup vs baseline: 1.0018x; 1.0018x over previous
#include <cuda_runtime.h>

#define BB 32
#define NN 4096
#define DD 256
#define HH 8
#define TT 28
#define ROWS (BB * NN)
#define BLK 128

// ---------- packed f32x2 FMA (sm_100+): 2 fp32 MACs per instruction ----------
__device__ __forceinline__ float2 ffma2(float2 a, float2 b, float2 c) {
    float2 d;
    asm("{\n\t"
        ".reg .b64 ra, rb, rc, rd;\n\t"
        "mov.b64 ra, {%2, %3};\n\t"
        "mov.b64 rb, {%4, %5};\n\t"
        "mov.b64 rc, {%6, %7};\n\t"
        "fma.rn.f32x2 rd, ra, rb, rc;\n\t"
        "mov.b64 {%0, %1}, rd;\n\t"
        "}"
        : "=f"(d.x), "=f"(d.y)
        : "f"(a.x), "f"(a.y), "f"(b.x), "f"(b.y), "f"(c.x), "f"(c.y));
    return d;
}

__device__ __forceinline__ float fex2(float x) {
    float y; asm("ex2.approx.f32 %0, %1;" : "=f"(y) : "f"(x)); return y;
}
__device__ __forceinline__ float frcp(float x) {
    float y; asm("rcp.approx.f32 %0, %1;" : "=f"(y) : "f"(x)); return y;
}

#define L2E 1.4426950408889634f

// sigmoid of both lanes, sharing one reciprocal: 2 EX2 + 1 RCP
__device__ __forceinline__ float2 sigmoid2(float2 v) {
    float ea = fex2(-L2E * v.x);
    float eb = fex2(-L2E * v.y);
    float sa = 1.0f + ea, sb = 1.0f + eb;
    float ip = frcp(sa * sb);
    return make_float2(sb * ip, sa * ip);
}

// tanh of both lanes via exp(2x), sharing one reciprocal
__device__ __forceinline__ float2 tanh2(float2 v) {
    float ta = fex2(2.0f * L2E * v.x);
    float tb = fex2(2.0f * L2E * v.y);
    float pa = ta + 1.0f, pb = tb + 1.0f;
    float ip = frcp(pa * pb);
    return make_float2((ta - 1.0f) * pb * ip, (tb - 1.0f) * pa * ip);
}

struct Smem {
    float4 xs[BLK][8];      // staged x chunk (128 rows x 32 cols), XOR-swizzled
    float4 wproj[DD][4];    // packed: [d][q] = rows 4q..4q+3 of [Wp;Wg1] at col d
    float4 whh[HH][6];      // [j][q] = W_hh rows 4q..4q+3, col j
    float4 wih[6];          // w_ih[24]
    float4 bih[6];
    float4 bhh[6];
    float4 wg2[TT][2];      // Wg2 row t (8 floats)
    float  bg2[TT];
    float2 wo2[4];          // Wo pairs
    float2 bp2[4];          // bp pairs
    float2 bg12[4];         // bg1 pairs
    float  dc[TT];          // decay curve
    float  bo;
};

__global__ void __launch_bounds__(BLK)
horizon_kernel(const float* __restrict__ x, const float* __restrict__ last_step,
               const float* __restrict__ W_ih, const float* __restrict__ W_hh,
               const float* __restrict__ b_ih, const float* __restrict__ b_hh,
               const float* __restrict__ Wp, const float* __restrict__ bp,
               const float* __restrict__ Wo, const float* __restrict__ bo,
               const float* __restrict__ Wg1, const float* __restrict__ bg1,
               const float* __restrict__ Wg2, const float* __restrict__ bg2,
               const float* __restrict__ log_decay, float* __restrict__ out) {
    __shared__ Smem s;
    const int tid = threadIdx.x;
    const int rb = blockIdx.x * BLK;

    // ---------------- weight prep (packed pair layouts) ----------------
    for (int i = tid; i < DD * 4; i += BLK) {
        int d = i >> 2, q = i & 3;
        const float* Wsrc = (q < 2) ? (Wp + (4 * q) * DD) : (Wg1 + (4 * q - 8) * DD);
        float4 w;
        w.x = Wsrc[d];
        w.y = Wsrc[DD + d];
        w.z = Wsrc[2 * DD + d];
        w.w = Wsrc[3 * DD + d];
        s.wproj[d][q] = w;
    }
    if (tid < 48) {
        int j = tid / 6, q = tid % 6;
        s.whh[j][q] = make_float4(W_hh[(4 * q + 0) * HH + j], W_hh[(4 * q + 1) * HH + j],
                                  W_hh[(4 * q + 2) * HH + j], W_hh[(4 * q + 3) * HH + j]);
    }
    if (tid < 6) {
        s.wih[tid] = ((const float4*)W_ih)[tid];
        s.bih[tid] = ((const float4*)b_ih)[tid];
        s.bhh[tid] = ((const float4*)b_hh)[tid];
    }
    if (tid < 56) s.wg2[tid >> 1][tid & 1] = ((const float4*)Wg2)[tid];
    if (tid < TT) {
        s.bg2[tid] = bg2[tid];
        float edc = __expf(log_decay[0]);
        s.dc[tid] = __expf(-edc * (float)(tid + 1));
    }
    if (tid < 4) {
        s.wo2[tid]  = ((const float2*)Wo)[tid];
        s.bp2[tid]  = ((const float2*)bp)[tid];
        s.bg12[tid] = ((const float2*)bg1)[tid];
    }
    if (tid == 0) s.bo = bo[0];
    __syncthreads();

    // ---------------- projections: h0 (Wp) and g1pre (Wg1) ----------------
    float2 acc[8];
#pragma unroll
    for (int p = 0; p < 4; p++) acc[p] = s.bp2[p];
#pragma unroll
    for (int p = 0; p < 4; p++) acc[4 + p] = s.bg12[p];

#pragma unroll 1
    for (int c = 0; c < 8; c++) {
        __syncthreads();
        // cooperative coalesced load of 128 rows x 32 cols
#pragma unroll
        for (int k = 0; k < 8; k++) {
            int idx = k * BLK + tid;          // 0..1023 float4s
            int r = idx >> 3, q = idx & 7;
            float4 v = ((const float4*)(x + (size_t)(rb + r) * DD + c * 32))[q];
            s.xs[r][q ^ (r & 7)] = v;
        }
        __syncthreads();
#pragma unroll
        for (int q = 0; q < 8; q++) {
            float4 xv = s.xs[tid][q ^ (tid & 7)];
            float xe0 = xv.x, xe1 = xv.y, xe2 = xv.z, xe3 = xv.w;
            const float4* wd = s.wproj[(c << 5) + (q << 2)];
#pragma unroll
            for (int e = 0; e < 4; e++) {
                float xs_e = (e == 0) ? xe0 : (e == 1) ? xe1 : (e == 2) ? xe2 : xe3;
                float2 xd = make_float2(xs_e, xs_e);
                float4 w0 = wd[e * 4 + 0], w1 = wd[e * 4 + 1];
                float4 w2 = wd[e * 4 + 2], w3 = wd[e * 4 + 3];
                acc[0] = ffma2(make_float2(w0.x, w0.y), xd, acc[0]);
                acc[1] = ffma2(make_float2(w0.z, w0.w), xd, acc[1]);
                acc[2] = ffma2(make_float2(w1.x, w1.y), xd, acc[2]);
                acc[3] = ffma2(make_float2(w1.z, w1.w), xd, acc[3]);
                acc[4] = ffma2(make_float2(w2.x, w2.y), xd, acc[4]);
                acc[5] = ffma2(make_float2(w2.z, w2.w), xd, acc[5]);
                acc[6] = ffma2(make_float2(w3.x, w3.y), xd, acc[6]);
                acc[7] = ffma2(make_float2(w3.z, w3.w), xd, acc[7]);
            }
        }
    }

    float2 h2[4];
#pragma unroll
    for (int p = 0; p < 4; p++) h2[p] = acc[p];
    float2 g1p[4];
#pragma unroll
    for (int p = 0; p < 4; p++)
        g1p[p] = make_float2(fmaxf(acc[4 + p].x, 0.0f), fmaxf(acc[4 + p].y, 0.0f));

    // ---------------- GRU rollout fused with gate + decay + output ----------------
    float last = last_step[rb + tid];
    float cur = last;
    float* outrow = out + (size_t)(rb + tid) * TT;
    float4 obuf = make_float4(0.f, 0.f, 0.f, 0.f);

#pragma unroll 4
    for (int t = 0; t < TT; t++) {
        // gh = h @ W_hh^T + b_hh  (12 packed pairs over k = 0..23)
        float2 g[12];
#pragma unroll
        for (int q = 0; q < 6; q++) {
            float4 b4 = s.bhh[q];
            g[2 * q]     = make_float2(b4.x, b4.y);
            g[2 * q + 1] = make_float2(b4.z, b4.w);
        }
#pragma unroll
        for (int j = 0; j < 8; j++) {
            float hj = (j & 1) ? h2[j >> 1].y : h2[j >> 1].x;
            float2 hd = make_float2(hj, hj);
#pragma unroll
            for (int q = 0; q < 6; q++) {
                float4 w4 = s.whh[j][q];
                g[2 * q]     = ffma2(make_float2(w4.x, w4.y), hd, g[2 * q]);
                g[2 * q + 1] = ffma2(make_float2(w4.z, w4.w), hd, g[2 * q + 1]);
            }
        }
        // gi = cur * w_ih + b_ih
        float2 curd = make_float2(cur, cur);
        float2 gi[12];
#pragma unroll
        for (int q = 0; q < 6; q++) {
            float4 wa = s.wih[q];
            float4 ba = s.bih[q];
            gi[2 * q]     = ffma2(make_float2(wa.x, wa.y), curd, make_float2(ba.x, ba.y));
            gi[2 * q + 1] = ffma2(make_float2(wa.z, wa.w), curd, make_float2(ba.z, ba.w));
        }
        // gates
        float2 r2[4], z2[4], n2[4];
#pragma unroll
        for (int p = 0; p < 4; p++)
            r2[p] = sigmoid2(make_float2(gi[p].x + g[p].x, gi[p].y + g[p].y));
#pragma unroll
        for (int p = 0; p < 4; p++)
            z2[p] = sigmoid2(make_float2(gi[4 + p].x + g[4 + p].x, gi[4 + p].y + g[4 + p].y));
#pragma unroll
        for (int p = 0; p < 4; p++)
            n2[p] = tanh2(ffma2(r2[p], g[8 + p], gi[8 + p]));
        // h_new = n + z*(h - n);  pred = h_new . Wo + bo
        float2 pacc = make_float2(0.0f, 0.0f);
#pragma unroll
        for (int p = 0; p < 4; p++) {
            float2 dmn = make_float2(h2[p].x - n2[p].x, h2[p].y - n2[p].y);
            float2 hn = ffma2(z2[p], dmn, n2[p]);
            h2[p] = hn;
            pacc = ffma2(hn, s.wo2[p], pacc);
        }
        float pred = pacc.x + pacc.y + s.bo;
        cur = pred;

        // gate_t = sigmoid(g1 . Wg2[t] + bg2[t])
        float4 wg0 = s.wg2[t][0], wg1v = s.wg2[t][1];
        float2 lacc = ffma2(g1p[0], make_float2(wg0.x, wg0.y), make_float2(s.bg2[t], 0.0f));
        lacc = ffma2(g1p[1], make_float2(wg0.z, wg0.w), lacc);
        lacc = ffma2(g1p[2], make_float2(wg1v.x, wg1v.y), lacc);
        lacc = ffma2(g1p[3], make_float2(wg1v.z, wg1v.w), lacc);
        float lg = lacc.x + lacc.y;
        float gate = frcp(1.0f + fex2(-L2E * lg));

        float gd = last * s.dc[t];
        float f = fmaf(gate, pred - gd, gd);  // gate*pred + (1-gate)*gd

        if ((t & 3) == 0) obuf.x = f;
        else if ((t & 3) == 1) obuf.y = f;
        else if ((t & 3) == 2) obuf.z = f;
        else {
            obuf.w = f;
            ((float4*)outrow)[t >> 2] = obuf;
        }
    }
}

extern "C" void kernel_launch(void* const* d_in, const int* in_sizes, int n_in,
                              void* d_out, int out_size) {
    const float* x         = (const float*)d_in[0];
    const float* last_step = (const float*)d_in[1];
    const float* W_ih      = (const float*)d_in[2];
    const float* W_hh      = (const float*)d_in[3];
    const float* b_ih      = (const float*)d_in[4];
    const float* b_hh      = (const float*)d_in[5];
    const float* Wp        = (const float*)d_in[6];
    const float* bp        = (const float*)d_in[7];
    const float* Wo        = (const float*)d_in[8];
    const float* bo        = (const float*)d_in[9];
    const float* Wg1       = (const float*)d_in[10];
    const float* bg1       = (const float*)d_in[11];
    const float* Wg2       = (const float*)d_in[12];
    const float* bg2       = (const float*)d_in[13];
    const float* log_decay = (const float*)d_in[14];
    float* out = (float*)d_out;

    horizon_kernel<<<ROWS / BLK, BLK>>>(x, last_step, W_ih, W_hh, b_ih, b_hh,
                                        Wp, bp, Wo, bo, Wg1, bg1, Wg2, bg2,
                                        log_decay, out);
}

// round 3
// speedup vs baseline: 1.0037x; 1.0018x over previous
#include <cuda_runtime.h>

#define BB 32
#define NN 4096
#define DD 256
#define HH 8
#define TT 28
#define ROWS (BB * NN)
#define BLK 128

// ---------- packed f32x2 FMA (sm_100+): 2 fp32 MACs per instruction ----------
__device__ __forceinline__ float2 ffma2(float2 a, float2 b, float2 c) {
    float2 d;
    asm("{\n\t"
        ".reg .b64 ra, rb, rc, rd;\n\t"
        "mov.b64 ra, {%2, %3};\n\t"
        "mov.b64 rb, {%4, %5};\n\t"
        "mov.b64 rc, {%6, %7};\n\t"
        "fma.rn.f32x2 rd, ra, rb, rc;\n\t"
        "mov.b64 {%0, %1}, rd;\n\t"
        "}"
        : "=f"(d.x), "=f"(d.y)
        : "f"(a.x), "f"(a.y), "f"(b.x), "f"(b.y), "f"(c.x), "f"(c.y));
    return d;
}

__device__ __forceinline__ float fex2(float x) {
    float y; asm("ex2.approx.f32 %0, %1;" : "=f"(y) : "f"(x)); return y;
}
__device__ __forceinline__ float frcp(float x) {
    float y; asm("rcp.approx.f32 %0, %1;" : "=f"(y) : "f"(x)); return y;
}

#define L2E 1.4426950408889634f

// sigmoid of both lanes, sharing one reciprocal: 2 EX2 + 1 RCP
__device__ __forceinline__ float2 sigmoid2(float2 v) {
    float ea = fex2(-L2E * v.x);
    float eb = fex2(-L2E * v.y);
    float sa = 1.0f + ea, sb = 1.0f + eb;
    float ip = frcp(sa * sb);
    return make_float2(sb * ip, sa * ip);
}

// tanh of both lanes via exp(2x), sharing one reciprocal
__device__ __forceinline__ float2 tanh2(float2 v) {
    float ta = fex2(2.0f * L2E * v.x);
    float tb = fex2(2.0f * L2E * v.y);
    float pa = ta + 1.0f, pb = tb + 1.0f;
    float ip = frcp(pa * pb);
    return make_float2((ta - 1.0f) * pb * ip, (tb - 1.0f) * pa * ip);
}

struct Smem {
    float4 xs[BLK][8];      // staged x chunk (128 rows x 32 cols), XOR-swizzled
    float4 wproj[DD][4];    // packed: [d][q] = rows 4q..4q+3 of [Wp;Wg1] at col d
    float4 whh[HH][6];      // [j][q] = W_hh rows 4q..4q+3, col j
    float4 wih[6];          // w_ih[24]
    float4 bih[6];
    float4 bhh[6];
    float4 wg2[TT][2];      // Wg2 row t (8 floats)
    float  bg2[TT];
    float2 wo2[4];          // Wo pairs
    float2 bp2[4];          // bp pairs
    float2 bg12[4];         // bg1 pairs
    float  dc[TT];          // decay curve
    float  bo;
};

__global__ void __launch_bounds__(BLK)
horizon_kernel(const float* __restrict__ x, const float* __restrict__ last_step,
               const float* __restrict__ W_ih, const float* __restrict__ W_hh,
               const float* __restrict__ b_ih, const float* __restrict__ b_hh,
               const float* __restrict__ Wp, const float* __restrict__ bp,
               const float* __restrict__ Wo, const float* __restrict__ bo,
               const float* __restrict__ Wg1, const float* __restrict__ bg1,
               const float* __restrict__ Wg2, const float* __restrict__ bg2,
               const float* __restrict__ log_decay, float* __restrict__ out) {
    __shared__ Smem s;
    const int tid = threadIdx.x;
    const int rb = blockIdx.x * BLK;

    // ---------------- weight prep (packed pair layouts) ----------------
    for (int i = tid; i < DD * 4; i += BLK) {
        int d = i >> 2, q = i & 3;
        const float* Wsrc = (q < 2) ? (Wp + (4 * q) * DD) : (Wg1 + (4 * q - 8) * DD);
        float4 w;
        w.x = Wsrc[d];
        w.y = Wsrc[DD + d];
        w.z = Wsrc[2 * DD + d];
        w.w = Wsrc[3 * DD + d];
        s.wproj[d][q] = w;
    }
    if (tid < 48) {
        int j = tid / 6, q = tid % 6;
        s.whh[j][q] = make_float4(W_hh[(4 * q + 0) * HH + j], W_hh[(4 * q + 1) * HH + j],
                                  W_hh[(4 * q + 2) * HH + j], W_hh[(4 * q + 3) * HH + j]);
    }
    if (tid < 6) {
        s.wih[tid] = ((const float4*)W_ih)[tid];
        s.bih[tid] = ((const float4*)b_ih)[tid];
        s.bhh[tid] = ((const float4*)b_hh)[tid];
    }
    if (tid < 56) s.wg2[tid >> 1][tid & 1] = ((const float4*)Wg2)[tid];
    if (tid < TT) {
        s.bg2[tid] = bg2[tid];
        float edc = __expf(log_decay[0]);
        s.dc[tid] = __expf(-edc * (float)(tid + 1));
    }
    if (tid < 4) {
        s.wo2[tid]  = ((const float2*)Wo)[tid];
        s.bp2[tid]  = ((const float2*)bp)[tid];
        s.bg12[tid] = ((const float2*)bg1)[tid];
    }
    if (tid == 0) s.bo = bo[0];
    __syncthreads();

    // ---------------- projections: h0 (Wp) and g1pre (Wg1) ----------------
    float2 acc[8];
#pragma unroll
    for (int p = 0; p < 4; p++) acc[p] = s.bp2[p];
#pragma unroll
    for (int p = 0; p < 4; p++) acc[4 + p] = s.bg12[p];

#pragma unroll 1
    for (int c = 0; c < 8; c++) {
        __syncthreads();
        // cooperative coalesced load of 128 rows x 32 cols
#pragma unroll
        for (int k = 0; k < 8; k++) {
            int idx = k * BLK + tid;          // 0..1023 float4s
            int r = idx >> 3, q = idx & 7;
            float4 v = ((const float4*)(x + (size_t)(rb + r) * DD + c * 32))[q];
            s.xs[r][q ^ (r & 7)] = v;
        }
        __syncthreads();
#pragma unroll
        for (int q = 0; q < 8; q++) {
            float4 xv = s.xs[tid][q ^ (tid & 7)];
            float xe0 = xv.x, xe1 = xv.y, xe2 = xv.z, xe3 = xv.w;
            const float4* wd = s.wproj[(c << 5) + (q << 2)];
#pragma unroll
            for (int e = 0; e < 4; e++) {
                float xs_e = (e == 0) ? xe0 : (e == 1) ? xe1 : (e == 2) ? xe2 : xe3;
                float2 xd = make_float2(xs_e, xs_e);
                float4 w0 = wd[e * 4 + 0], w1 = wd[e * 4 + 1];
                float4 w2 = wd[e * 4 + 2], w3 = wd[e * 4 + 3];
                acc[0] = ffma2(make_float2(w0.x, w0.y), xd, acc[0]);
                acc[1] = ffma2(make_float2(w0.z, w0.w), xd, acc[1]);
                acc[2] = ffma2(make_float2(w1.x, w1.y), xd, acc[2]);
                acc[3] = ffma2(make_float2(w1.z, w1.w), xd, acc[3]);
                acc[4] = ffma2(make_float2(w2.x, w2.y), xd, acc[4]);
                acc[5] = ffma2(make_float2(w2.z, w2.w), xd, acc[5]);
                acc[6] = ffma2(make_float2(w3.x, w3.y), xd, acc[6]);
                acc[7] = ffma2(make_float2(w3.z, w3.w), xd, acc[7]);
            }
        }
    }

    float2 h2[4];
#pragma unroll
    for (int p = 0; p < 4; p++) h2[p] = acc[p];
    float2 g1p[4];
#pragma unroll
    for (int p = 0; p < 4; p++)
        g1p[p] = make_float2(fmaxf(acc[4 + p].x, 0.0f), fmaxf(acc[4 + p].y, 0.0f));

    // ---------------- GRU rollout fused with gate + decay + output ----------------
    float last = last_step[rb + tid];
    float cur = last;
    float* outrow = out + (size_t)(rb + tid) * TT;
    float4 obuf = make_float4(0.f, 0.f, 0.f, 0.f);

#pragma unroll 4
    for (int t = 0; t < TT; t++) {
        // gh = h @ W_hh^T + b_hh  (12 packed pairs over k = 0..23)
        float2 g[12];
#pragma unroll
        for (int q = 0; q < 6; q++) {
            float4 b4 = s.bhh[q];
            g[2 * q]     = make_float2(b4.x, b4.y);
            g[2 * q + 1] = make_float2(b4.z, b4.w);
        }
#pragma unroll
        for (int j = 0; j < 8; j++) {
            float hj = (j & 1) ? h2[j >> 1].y : h2[j >> 1].x;
            float2 hd = make_float2(hj, hj);
#pragma unroll
            for (int q = 0; q < 6; q++) {
                float4 w4 = s.whh[j][q];
                g[2 * q]     = ffma2(make_float2(w4.x, w4.y), hd, g[2 * q]);
                g[2 * q + 1] = ffma2(make_float2(w4.z, w4.w), hd, g[2 * q + 1]);
            }
        }
        // gi = cur * w_ih + b_ih
        float2 curd = make_float2(cur, cur);
        float2 gi[12];
#pragma unroll
        for (int q = 0; q < 6; q++) {
            float4 wa = s.wih[q];
            float4 ba = s.bih[q];
            gi[2 * q]     = ffma2(make_float2(wa.x, wa.y), curd, make_float2(ba.x, ba.y));
            gi[2 * q + 1] = ffma2(make_float2(wa.z, wa.w), curd, make_float2(ba.z, ba.w));
        }
        // gates
        float2 r2[4], z2[4], n2[4];
#pragma unroll
        for (int p = 0; p < 4; p++)
            r2[p] = sigmoid2(make_float2(gi[p].x + g[p].x, gi[p].y + g[p].y));
#pragma unroll
        for (int p = 0; p < 4; p++)
            z2[p] = sigmoid2(make_float2(gi[4 + p].x + g[4 + p].x, gi[4 + p].y + g[4 + p].y));
#pragma unroll
        for (int p = 0; p < 4; p++)
            n2[p] = tanh2(ffma2(r2[p], g[8 + p], gi[8 + p]));
        // h_new = n + z*(h - n);  pred = h_new . Wo + bo
        float2 pacc = make_float2(0.0f, 0.0f);
#pragma unroll
        for (int p = 0; p < 4; p++) {
            float2 dmn = make_float2(h2[p].x - n2[p].x, h2[p].y - n2[p].y);
            float2 hn = ffma2(z2[p], dmn, n2[p]);
            h2[p] = hn;
            pacc = ffma2(hn, s.wo2[p], pacc);
        }
        float pred = pacc.x + pacc.y + s.bo;
        cur = pred;

        // gate_t = sigmoid(g1 . Wg2[t] + bg2[t])
        float4 wg0 = s.wg2[t][0], wg1v = s.wg2[t][1];
        float2 lacc = ffma2(g1p[0], make_float2(wg0.x, wg0.y), make_float2(s.bg2[t], 0.0f));
        lacc = ffma2(g1p[1], make_float2(wg0.z, wg0.w), lacc);
        lacc = ffma2(g1p[2], make_float2(wg1v.x, wg1v.y), lacc);
        lacc = ffma2(g1p[3], make_float2(wg1v.z, wg1v.w), lacc);
        float lg = lacc.x + lacc.y;
        float gate = frcp(1.0f + fex2(-L2E * lg));

        float gd = last * s.dc[t];
        float f = fmaf(gate, pred - gd, gd);  // gate*pred + (1-gate)*gd

        if ((t & 3) == 0) obuf.x = f;
        else if ((t & 3) == 1) obuf.y = f;
        else if ((t & 3) == 2) obuf.z = f;
        else {
            obuf.w = f;
            ((float4*)outrow)[t >> 2] = obuf;
        }
    }
}

extern "C" void kernel_launch(void* const* d_in, const int* in_sizes, int n_in,
                              void* d_out, int out_size) {
    const float* x         = (const float*)d_in[0];
    const float* last_step = (const float*)d_in[1];
    const float* W_ih      = (const float*)d_in[2];
    const float* W_hh      = (const float*)d_in[3];
    const float* b_ih      = (const float*)d_in[4];
    const float* b_hh      = (const float*)d_in[5];
    const float* Wp        = (const float*)d_in[6];
    const float* bp        = (const float*)d_in[7];
    const float* Wo        = (const float*)d_in[8];
    const float* bo        = (const float*)d_in[9];
    const float* Wg1       = (const float*)d_in[10];
    const float* bg1       = (const float*)d_in[11];
    const float* Wg2       = (const float*)d_in[12];
    const float* bg2       = (const float*)d_in[13];
    const float* log_decay = (const float*)d_in[14];
    float* out = (float*)d_out;

    horizon_kernel<<<ROWS / BLK, BLK>>>(x, last_step, W_ih, W_hh, b_ih, b_hh,
                                        Wp, bp, Wo, bo, Wg1, bg1, Wg2, bg2,
                                        log_decay, out);
}